// round 1
// baseline (speedup 1.0000x reference)
#include <cuda_runtime.h>

// PyramidDownSampling: x (2,1,256,256,256) f32
//   out = [ x copy | d1 = blur3 stride2 (2,1,128^3) | d2 = blur5 stride4 (2,1,64^3) ]
// Edge ("replicate") padding by k//2 on each spatial dim.
// Fused single pass: each block loads an 8x8x64 input tile (+2 halo all sides)
// into smem once, then emits the copy, the d1 outputs (4x4x32) and the d2
// outputs (2x2x16) from shared memory. DRAM traffic ~= 1x read + all writes.

#define S   256
#define NB  2
#define TD  8
#define TH  8
#define TW  64
#define SD  (TD + 4)   // 12
#define SH  (TH + 4)   // 12
#define SW  (TW + 4)   // 68
#define SMEM_ELEMS (SD * SH * SW)   // 9792 floats = 38.25 KB

__global__ __launch_bounds__(256)
void pyramid_fused_kernel(const float* __restrict__ x,
                          const float* __restrict__ k0,   // 27 floats (3x3x3)
                          const float* __restrict__ k1,   // 125 floats (5x5x5)
                          float* __restrict__ out)
{
    __shared__ float sm[SMEM_ELEMS];
    __shared__ float sk0[27];
    __shared__ float sk1[125];

    const int tid = threadIdx.x;
    const int bz  = blockIdx.z;          // n * (S/TD) + z-chunk
    const int n   = bz >> 5;             // S/TD = 32
    const int z0  = (bz & 31) * TD;
    const int y0  = blockIdx.y * TH;
    const int x0  = blockIdx.x * TW;

    // stage the (symmetric, separable) kernels into smem
    if (tid < 27)            sk0[tid]      = k0[tid];
    else if (tid < 27 + 125) sk1[tid - 27] = k1[tid - 27];

    const float* xn = x + (size_t)n * S * S * S;

    // ---- load tile + halo (edge-clamped) ----
    for (int idx = tid; idx < SMEM_ELEMS; idx += 256) {
        int dz = idx / (SH * SW);
        int r  = idx % (SH * SW);
        int dy = r / SW;
        int dx = r % SW;
        int gz = z0 - 2 + dz; gz = min(max(gz, 0), S - 1);
        int gy = y0 - 2 + dy; gy = min(max(gy, 0), S - 1);
        int gx = x0 - 2 + dx; gx = min(max(gx, 0), S - 1);
        sm[idx] = __ldg(&xn[((size_t)gz * S + gy) * S + gx]);
    }
    __syncthreads();

    // ---- 1) identity copy of x (float4 stores, 16 per row of 64) ----
    {
        float* outx = out + (size_t)n * S * S * S;
        #pragma unroll 4
        for (int idx = tid; idx < TD * TH * (TW / 4); idx += 256) {
            int lw = idx & 15;           // float4 index in row
            int ly = (idx >> 4) & 7;
            int lz = idx >> 7;
            const float* sp = &sm[((lz + 2) * SH + (ly + 2)) * SW + 2 + 4 * lw];
            float4 v = make_float4(sp[0], sp[1], sp[2], sp[3]);
            *(float4*)&outx[((size_t)(z0 + lz) * S + (y0 + ly)) * S + x0 + 4 * lw] = v;
        }
    }

    // ---- 2) d1: 3x3x3 blur, stride 2 -> (128,128,128) ----
    {
        const int H1 = S / 2;
        float* out1 = out + (size_t)NB * S * S * S + (size_t)n * H1 * H1 * H1;
        // 4 x 4 x 32 = 512 outputs, 2 per thread
        #pragma unroll 2
        for (int t = tid; t < 512; t += 256) {
            int l = t & 31;              // ow within tile
            int j = (t >> 5) & 3;        // oh
            int i = t >> 7;              // od
            // global window start z = 2*od-1 = z0 + 2i - 1  ->  smem dz = 2i+1
            const int base = ((2 * i + 1) * SH + (2 * j + 1)) * SW + (2 * l + 1);
            float acc = 0.f;
            #pragma unroll
            for (int a = 0; a < 3; a++)
                #pragma unroll
                for (int b = 0; b < 3; b++)
                    #pragma unroll
                    for (int c = 0; c < 3; c++)
                        acc += sk0[(a * 3 + b) * 3 + c] *
                               sm[base + (a * SH + b) * SW + c];
            int od = (z0 >> 1) + i, oh = (y0 >> 1) + j, ow = (x0 >> 1) + l;
            out1[((size_t)od * H1 + oh) * H1 + ow] = acc;
        }
    }

    // ---- 3) d2: 5x5x5 blur, stride 4 -> (64,64,64) ----
    {
        const int H2 = S / 4;
        float* out2 = out + (size_t)NB * S * S * S
                          + (size_t)NB * (S / 2) * (S / 2) * (S / 2)
                          + (size_t)n * H2 * H2 * H2;
        if (tid < 64) {                  // 2 x 2 x 16 = 64 outputs
            int l = tid & 15;
            int j = (tid >> 4) & 1;
            int i = tid >> 5;
            // global window start z = 4*od-2 = z0 + 4i - 2  ->  smem dz = 4i
            const int base = ((4 * i) * SH + (4 * j)) * SW + (4 * l);
            float acc = 0.f;
            #pragma unroll
            for (int a = 0; a < 5; a++)
                #pragma unroll
                for (int b = 0; b < 5; b++)
                    #pragma unroll
                    for (int c = 0; c < 5; c++)
                        acc += sk1[(a * 5 + b) * 5 + c] *
                               sm[base + (a * SH + b) * SW + c];
            int od = (z0 >> 2) + i, oh = (y0 >> 2) + j, ow = (x0 >> 2) + l;
            out2[((size_t)od * H2 + oh) * H2 + ow] = acc;
        }
    }
}

extern "C" void kernel_launch(void* const* d_in, const int* in_sizes, int n_in,
                              void* d_out, int out_size)
{
    const float* x  = (const float*)d_in[0];
    const float* k0 = (const float*)d_in[1];
    const float* k1 = (const float*)d_in[2];
    float* out = (float*)d_out;

    dim3 grid(S / TW, S / TH, NB * (S / TD));   // (4, 32, 64)
    pyramid_fused_kernel<<<grid, 256>>>(x, k0, k1, out);
}

// round 2
// speedup vs baseline: 1.2166x; 1.2166x over previous
#include <cuda_runtime.h>

// PyramidDownSampling fused: out = [ x copy | 3^3 s2 blur (128^3) | 5^3 s4 blur (64^3) ]
// R2: row-oriented vectorized halo load (per-row index math, float4 bulk),
//     padded smem rows for aligned STS.128, streaming output stores.

#define S   256
#define NB  2
#define TD  8
#define TH  8
#define TW  64
#define SD  (TD + 4)   // 12
#define SH  (TH + 4)   // 12
#define SW  72          // padded row: cols 2..69 hold logical dx 0..67
#define NROWS (SD * SH) // 144
#define SMEM_ELEMS (NROWS * SW)  // 10368 floats = 40.5 KB

__global__ __launch_bounds__(256)
void pyramid_fused_kernel(const float* __restrict__ x,
                          const float* __restrict__ k0,   // 27 floats (3x3x3)
                          const float* __restrict__ k1,   // 125 floats (5x5x5)
                          float* __restrict__ out)
{
    __shared__ __align__(16) float sm[SMEM_ELEMS];
    __shared__ float sk0[27];
    __shared__ float sk1[125];

    const int tid = threadIdx.x;
    const int bz  = blockIdx.z;          // n * 32 + z-chunk
    const int n   = bz >> 5;
    const int z0  = (bz & 31) * TD;
    const int y0  = blockIdx.y * TH;
    const int x0  = blockIdx.x * TW;

    if (tid < 27)            sk0[tid]      = k0[tid];
    else if (tid < 27 + 125) sk1[tid - 27] = k1[tid - 27];

    const float* xn = x + (size_t)n * S * S * S;

    // ---- load tile + halo: 4 threads per smem row, float4 interior ----
    // logical dx 0..67 -> smem col dx+2 ; interior (gx = x0..x0+63) -> cols 4..67
    for (int slot = tid; slot < NROWS * 4; slot += 256) {
        const int lane = slot & 3;
        const int row  = slot >> 2;
        const int dz   = row / SH;          // /12, once per 16 floats
        const int dy   = row - dz * SH;
        int gz = z0 - 2 + dz; gz = min(max(gz, 0), S - 1);
        int gy = y0 - 2 + dy; gy = min(max(gy, 0), S - 1);
        const float* gp = xn + ((size_t)gz * S + gy) * S;   // global row
        float* srow = &sm[row * SW];

        const float4* g4 = (const float4*)(gp + x0);
        float4* s4 = (float4*)(srow + 4);
        #pragma unroll
        for (int v = 0; v < 4; v++)
            s4[lane * 4 + v] = g4[lane * 4 + v];

        if (lane == 0) {   // 4 edge-clamped halo scalars
            srow[2]  = gp[max(x0 - 2, 0)];
            srow[3]  = gp[max(x0 - 1, 0)];
            srow[68] = gp[min(x0 + 64, S - 1)];
            srow[69] = gp[min(x0 + 65, S - 1)];
        }
    }
    __syncthreads();

    // ---- 1) identity copy (float4, streaming) ----
    {
        float* outx = out + (size_t)n * S * S * S;
        #pragma unroll
        for (int q = 0; q < 4; q++) {
            int idx = tid + q * 256;             // 1024 float4s total
            int lw = idx & 15;                   // float4 within row
            int ly = (idx >> 4) & 7;
            int lz = idx >> 7;
            const float4* sp = (const float4*)&sm[((lz + 2) * SH + (ly + 2)) * SW + 4];
            float4 v = sp[lw];
            float4* op = (float4*)&outx[((size_t)(z0 + lz) * S + (y0 + ly)) * S + x0];
            __stcs(&op[lw], v);
        }
    }

    // ---- 2) d1: 3x3x3 blur stride 2 -> (128^3) ----
    {
        const int H1 = S / 2;
        float* out1 = out + (size_t)NB * S * S * S + (size_t)n * H1 * H1 * H1
                    + (((size_t)(z0 >> 1) * H1 + (y0 >> 1)) * H1 + (x0 >> 1));
        #pragma unroll
        for (int q = 0; q < 2; q++) {
            int t = tid + q * 256;               // 512 outputs
            int l = t & 31;
            int j = (t >> 5) & 3;
            int i = t >> 7;
            // window start z = z0+2i-1 -> smem dz = 2i+1 ; x -> smem col 2l+1+2
            const int base = ((2 * i + 1) * SH + (2 * j + 1)) * SW + (2 * l + 3);
            float acc = 0.f;
            #pragma unroll
            for (int a = 0; a < 3; a++)
                #pragma unroll
                for (int b = 0; b < 3; b++)
                    #pragma unroll
                    for (int c = 0; c < 3; c++)
                        acc += sk0[(a * 3 + b) * 3 + c] * sm[base + (a * SH + b) * SW + c];
            __stcs(&out1[((size_t)i * H1 + j) * H1 + l], acc);
        }
    }

    // ---- 3) d2: 5x5x5 blur stride 4 -> (64^3) ----
    {
        const int H2 = S / 4;
        float* out2 = out + (size_t)NB * S * S * S
                          + (size_t)NB * (S / 2) * (S / 2) * (S / 2)
                          + (size_t)n * H2 * H2 * H2
                          + (((size_t)(z0 >> 2) * H2 + (y0 >> 2)) * H2 + (x0 >> 2));
        if (tid < 64) {                          // 2 x 2 x 16 outputs
            int l = tid & 15;
            int j = (tid >> 4) & 1;
            int i = tid >> 5;
            // window start z = z0+4i-2 -> smem dz = 4i ; x -> smem col 4l+2
            const int base = ((4 * i) * SH + (4 * j)) * SW + (4 * l + 2);
            float acc = 0.f;
            #pragma unroll
            for (int a = 0; a < 5; a++)
                #pragma unroll
                for (int b = 0; b < 5; b++)
                    #pragma unroll
                    for (int c = 0; c < 5; c++)
                        acc += sk1[(a * 5 + b) * 5 + c] * sm[base + (a * SH + b) * SW + c];
            __stcs(&out2[((size_t)i * H2 + j) * H2 + l], acc);
        }
    }
}

extern "C" void kernel_launch(void* const* d_in, const int* in_sizes, int n_in,
                              void* d_out, int out_size)
{
    const float* x  = (const float*)d_in[0];
    const float* k0 = (const float*)d_in[1];
    const float* k1 = (const float*)d_in[2];
    float* out = (float*)d_out;

    dim3 grid(S / TW, S / TH, NB * (S / TD));   // (4, 32, 64)
    pyramid_fused_kernel<<<grid, 256>>>(x, k0, k1, out);
}